// round 13
// baseline (speedup 1.0000x reference)
#include <cuda_runtime.h>
#include <cuda_fp16.h>
#include <cstdint>

#define BATCH     512
#define SIZE_IN   1024
#define SIZE_OUT  256
#define NQ        16

#define BT        64                 // batch tile per CTA
#define ISPLIT    37                 // 8 * 37 = 296 = 148 SMs * 2 CTAs exactly
#define NPHMAX    14                 // ceil(28/2)
#define NTHREADS  512
#define SLOT_B    16384              // bytes per ring slot (2 features x 16 rows x 512 B)
#define RING_B    (3 * SLOT_B)       // 48 KB dynamic smem

// fp16 copy of the weight table (8 MB static scratch; no allocation allowed)
__device__ __half g_tableh[NQ * SIZE_IN * SIZE_OUT];

// Fused prep: table fp32 -> fp16 (16 elems/thread, 4 front-batched LDG.128)
// + bias init of out (first 512 blocks write one output row each).
__global__ void il_prep(const float* __restrict__ table,
                        const float* __restrict__ bias,
                        float* __restrict__ out) {
    const size_t i = ((size_t)blockIdx.x * blockDim.x + threadIdx.x) * 16;
    const float4 a0 = *reinterpret_cast<const float4*>(table + i);
    const float4 a1 = *reinterpret_cast<const float4*>(table + i + 4);
    const float4 a2 = *reinterpret_cast<const float4*>(table + i + 8);
    const float4 a3 = *reinterpret_cast<const float4*>(table + i + 12);
    __half2 h[8];
    h[0] = __floats2half2_rn(a0.x, a0.y); h[1] = __floats2half2_rn(a0.z, a0.w);
    h[2] = __floats2half2_rn(a1.x, a1.y); h[3] = __floats2half2_rn(a1.z, a1.w);
    h[4] = __floats2half2_rn(a2.x, a2.y); h[5] = __floats2half2_rn(a2.z, a2.w);
    h[6] = __floats2half2_rn(a3.x, a3.y); h[7] = __floats2half2_rn(a3.z, a3.w);
    *reinterpret_cast<uint4*>(g_tableh + i)     = *reinterpret_cast<uint4*>(h);
    *reinterpret_cast<uint4*>(g_tableh + i + 8) = *reinterpret_cast<uint4*>(h + 4);

    if (blockIdx.x < BATCH) {   // out[b, o] = bias[o]
        out[blockIdx.x * SIZE_OUT + threadIdx.x] = bias[threadIdx.x];
    }
}

__device__ __forceinline__ void cp_async16(uint32_t saddr, const void* gptr) {
    asm volatile("cp.async.cg.shared.global [%0], [%1], 16;\n" :: "r"(saddr), "l"(gptr));
}
__device__ __forceinline__ void cp_commit() {
    asm volatile("cp.async.commit_group;\n" ::: "memory");
}
__device__ __forceinline__ void red_v4(float* p, float a, float b, float c, float d) {
    asm volatile("red.global.add.v4.f32 [%0], {%1, %2, %3, %4};"
                 :: "l"(p), "f"(a), "f"(b), "f"(c), "f"(d) : "memory");
}

// One CTA: 64 batches x (27..28) features x 256 outputs.
// Ring-3 of 16 KB phase buffers (2 features each); one cp.async commit group
// per phase, wait_group 1 keeps a full phase of prefetch in flight.
__global__ __launch_bounds__(NTHREADS, 2)
void il_main(const float* __restrict__ x,
             const int* __restrict__ indices,   // JAX canonicalizes int64 -> int32
             float* __restrict__ out) {
    extern __shared__ __align__(16) __half sW[];   // 3 x 8192 halves (48 KB)
    __shared__ float4 sxq[BT][NPHMAX];   // {x0, bits(q0*256), x1, bits(q1*256)}

    const int b0  = blockIdx.x * BT;
    const int lo  = (int)(((long long)blockIdx.y * SIZE_IN) / ISPLIT);
    const int hi  = (int)(((long long)(blockIdx.y + 1) * SIZE_IN) / ISPLIT);
    const int len = hi - lo;             // 27 or 28
    const int nph = (len + 1) >> 1;      // 14
    const int t   = threadIdx.x;
    const int og  = t & 31;              // output columns og*8 .. og*8+7
    const int bg  = t >> 5;              // batches bg*4 .. bg*4+3 (warp-uniform)

    const uint32_t sW_u32 = (uint32_t)__cvta_generic_to_shared(sW);
    const int sq = t >> 5;               // staged row 0..15
    const int sc = t & 31;               // 16B chunk within the 512 B row
    const uint32_t lane_off = (uint32_t)(sq * 512 + sc * 16);

    // Prefetch phases 0 and 1 (slots 0, 1), one commit group each.
    #pragma unroll
    for (int p0 = 0; p0 < 2; p0++) {
        if (p0 < nph) {
            const int i0 = lo + 2 * p0;
            const uint32_t dst = sW_u32 + (uint32_t)p0 * SLOT_B + lane_off;
            const __half* src = g_tableh + ((size_t)sq * SIZE_IN + i0) * SIZE_OUT + sc * 8;
            cp_async16(dst, src);
            if (i0 + 1 < hi) cp_async16(dst + 8192u, src + SIZE_OUT);
        }
        cp_commit();
    }

    // Preload sxq: thread covers batch bl = t>>3, phases (t&7) + 8k.
    {
        const int bl = t >> 3;
        const float* xp = x       + (size_t)(b0 + bl) * SIZE_IN;
        const int*   qp = indices + (size_t)(b0 + bl) * SIZE_IN;
        #pragma unroll
        for (int k = 0; k < 2; k++) {
            const int p = (t & 7) + k * 8;
            if (p < nph) {
                const int i0 = lo + 2 * p;
                float4 v;
                v.x = xp[i0];
                v.y = __int_as_float(qp[i0] * SIZE_OUT);
                if (i0 + 1 < hi) {
                    v.z = xp[i0 + 1];
                    v.w = __int_as_float(qp[i0 + 1] * SIZE_OUT);
                } else {
                    v.z = 0.f;
                    v.w = __int_as_float(0);
                }
                sxq[bl][p] = v;
            }
        }
    }

    float acc[4][8];
    #pragma unroll
    for (int bl = 0; bl < 4; bl++)
        #pragma unroll
        for (int c = 0; c < 8; c++) acc[bl][c] = 0.f;

    uint32_t curB = 0;   // byte offset of slot p%3: cycles 0, 16384, 32768
    for (int p = 0; p < nph; p++) {
        // Retire this phase's group; keep the next phase's group in flight.
        if (p + 1 < nph) asm volatile("cp.async.wait_group 1;" ::: "memory");
        else             asm volatile("cp.async.wait_group 0;" ::: "memory");
        __syncthreads();   // staged data visible; all readers done with slot (p+2)%3

        // Prefetch phase p+2 into slot (p+2)%3 (just freed).
        if (p + 2 < nph) {
            const int i0 = lo + 2 * (p + 2);
            uint32_t nextB = curB + 2u * SLOT_B;
            if (nextB >= RING_B) nextB -= RING_B;
            const uint32_t dst = sW_u32 + nextB + lane_off;
            const __half* src = g_tableh + ((size_t)sq * SIZE_IN + i0) * SIZE_OUT + sc * 8;
            cp_async16(dst, src);
            if (i0 + 1 < hi) cp_async16(dst + 8192u, src + SIZE_OUT);
            cp_commit();
        }

        const __half* wb  = sW + (curB >> 1);   // curB bytes -> halves
        const bool    two = (2 * p + 1 < len);

        float4 v[4];
        #pragma unroll
        for (int bl = 0; bl < 4; bl++) v[bl] = sxq[bg * 4 + bl][p];   // 16B broadcast

        // feature 0 of the phase
        #pragma unroll
        for (int bl = 0; bl < 4; bl++) {
            const uint4 u = *reinterpret_cast<const uint4*>(
                wb + __float_as_int(v[bl].y) + og * 8);
            const __half2* hp = reinterpret_cast<const __half2*>(&u);
            #pragma unroll
            for (int q = 0; q < 4; q++) {
                const float2 f = __half22float2(hp[q]);
                acc[bl][q * 2 + 0] += v[bl].x * f.x;
                acc[bl][q * 2 + 1] += v[bl].x * f.y;
            }
        }
        // feature 1 of the phase
        if (two) {
            #pragma unroll
            for (int bl = 0; bl < 4; bl++) {
                const uint4 u = *reinterpret_cast<const uint4*>(
                    wb + 4096 + __float_as_int(v[bl].w) + og * 8);
                const __half2* hp = reinterpret_cast<const __half2*>(&u);
                #pragma unroll
                for (int q = 0; q < 4; q++) {
                    const float2 f = __half22float2(hp[q]);
                    acc[bl][q * 2 + 0] += v[bl].z * f.x;
                    acc[bl][q * 2 + 1] += v[bl].z * f.y;
                }
            }
        }

        curB += SLOT_B;
        if (curB == RING_B) curB = 0;
    }

    // Combine split-k partials: 2 vectorized reductions per batch.
    #pragma unroll
    for (int bl = 0; bl < 4; bl++) {
        const int b = b0 + bg * 4 + bl;
        float* op = out + (size_t)b * SIZE_OUT + og * 8;
        red_v4(op,     acc[bl][0], acc[bl][1], acc[bl][2], acc[bl][3]);
        red_v4(op + 4, acc[bl][4], acc[bl][5], acc[bl][6], acc[bl][7]);
    }
}

extern "C" void kernel_launch(void* const* d_in, const int* in_sizes, int n_in,
                              void* d_out, int out_size) {
    const float* x       = (const float*)d_in[0];
    const int*   indices = (const int*)d_in[1];
    const float* table   = (const float*)d_in[2];
    const float* bias    = (const float*)d_in[3];
    float*       out     = (float*)d_out;

    static int attr_set = 0;
    if (!attr_set) {
        cudaFuncSetAttribute(il_main, cudaFuncAttributeMaxDynamicSharedMemorySize, RING_B);
        attr_set = 1;
    }

    // fused prep: 4,194,304 elems / 16 per thread / 256 per block = 1024 blocks
    il_prep<<<1024, 256>>>(table, bias, out);

    dim3 grid(BATCH / BT, ISPLIT);   // 8 x 37 = 296 CTAs = 148 SMs * 2
    il_main<<<grid, NTHREADS, RING_B>>>(x, indices, out);
}